// round 3
// baseline (speedup 1.0000x reference)
#include <cuda_runtime.h>
#include <cuda_bf16.h>

#define FLAT 524288          // 128 * 64 * 64

// ---------------- device scratch (no allocation) ----------------
__device__ float g_partA[512 * 1024];                 // [blk][sq(32)][b(32)]
__device__ float g_ev[4 * 32 * 8];                    // [s][b][q]
__device__ float g_G2[(size_t)128 * 4096 * 36];       // [o][ij][k]  ~75.5 MB

// ---------------- packed f32x2 helpers ----------------
typedef unsigned long long ull;
__device__ __forceinline__ ull pack2(float a, float b) {
    ull r; asm("mov.b64 %0, {%1,%2};" : "=l"(r) : "f"(a), "f"(b)); return r;
}
__device__ __forceinline__ void unpack2(ull v, float& a, float& b) {
    asm("mov.b64 {%0,%1}, %2;" : "=f"(a), "=f"(b) : "l"(v));
}
__device__ __forceinline__ ull ffma2(ull a, ull b, ull c) {
    ull d; asm("fma.rn.f32x2 %0, %1, %2, %3;" : "=l"(d) : "l"(a), "l"(b), "l"(c));
    return d;
}

// =========================================================================
// kA: stage-A partial reductions of q_in over (c, 16 subband rows).
// grid 512 = (c:128) x (igroup:4), 256 threads.
// =========================================================================
__global__ __launch_bounds__(256) void kA(const float* __restrict__ x,
                                          const float* __restrict__ Win) {
    int bx = blockIdx.x;
    int c = bx >> 2;
    int i0 = (bx & 3) << 4;
    int t = threadIdx.x, w = t >> 5, l = t & 31;

    __shared__ float subS[4][64][33];   // [s][j][b]
    __shared__ float Ws[64][36];        // [j][sq]

    float acc0 = 0.f, acc1 = 0.f, acc2 = 0.f, acc3 = 0.f;
    int s_w = w >> 1;

    for (int ii = 0; ii < 16; ++ii) {
        int i = i0 + ii;
        const float* wp = Win + (size_t)c * 4096 + (size_t)i * 64;
        for (int idx = t; idx < 2048; idx += 256) {
            int sq = idx >> 6, j = idx & 63;
            Ws[j][sq] = wp[(size_t)sq * FLAT + j];
        }
        for (int pass = 0; pass < 4; ++pass) {
            int b = w + pass * 8;
            const float* xp = x + ((((size_t)b * 128 + c) * 128) + 2 * i) * 128;
            float4 r0 = *(const float4*)(xp + 4 * l);
            float4 r1 = *(const float4*)(xp + 128 + 4 * l);
            int j0 = 2 * l;
            float a = r0.x, bb = r0.y, cc = r1.x, dd = r1.y;
            subS[0][j0][b] = 0.5f * (a + bb + cc + dd);
            subS[1][j0][b] = 0.5f * (a + bb - cc - dd);
            subS[2][j0][b] = 0.5f * (a - bb + cc - dd);
            subS[3][j0][b] = 0.5f * (a - bb - cc + dd);
            a = r0.z; bb = r0.w; cc = r1.z; dd = r1.w;
            subS[0][j0 + 1][b] = 0.5f * (a + bb + cc + dd);
            subS[1][j0 + 1][b] = 0.5f * (a + bb - cc - dd);
            subS[2][j0 + 1][b] = 0.5f * (a - bb + cc - dd);
            subS[3][j0 + 1][b] = 0.5f * (a - bb - cc + dd);
        }
        __syncthreads();
#pragma unroll 8
        for (int j = 0; j < 64; ++j) {
            float4 wv = *(const float4*)&Ws[j][w * 4];
            float sv = subS[s_w][j][l];
            acc0 = fmaf(sv, wv.x, acc0);
            acc1 = fmaf(sv, wv.y, acc1);
            acc2 = fmaf(sv, wv.z, acc2);
            acc3 = fmaf(sv, wv.w, acc3);
        }
        __syncthreads();
    }
    float* op = g_partA + (size_t)bx * 1024 + (w * 4) * 32 + l;
    op[0] = acc0; op[32] = acc1; op[64] = acc2; op[96] = acc3;
}

// =========================================================================
// kG: G2[o][ij][k] = 0.5 * sum_c fuseW[o,c] * B[c,ij,k]   (packed f32x2 FMA)
//   k = s*8+q  -> q_out_W[s][(c,ij)][q];  k = 32+s -> q_out_b[s][(c,ij)]
// grid (ijg:128, kg:9), 256 threads. K chunked by 32.
// =========================================================================
__global__ __launch_bounds__(256) void kG(const float* __restrict__ fuseW,
                                          const float* __restrict__ Wout,
                                          const float* __restrict__ bout) {
    __shared__ float As[32][132];   // [cc][o]
    __shared__ float Bs[32][128];   // [cc][ij'*4+kk]
    int ijg = blockIdx.x;           // 0..127
    int kg = blockIdx.y;            // 0..8
    int ij0 = ijg * 32;
    int t = threadIdx.x;
    int to = t & 31, tn = t >> 5;

    ull acc[4][8];
#pragma unroll
    for (int a = 0; a < 4; ++a)
#pragma unroll
        for (int m = 0; m < 8; ++m) acc[a][m] = pack2(0.f, 0.f);

    for (int c0 = 0; c0 < 128; c0 += 32) {
        for (int idx = t; idx < 4096; idx += 256) {
            int o = idx >> 5, cc = idx & 31;
            As[cc][o] = fuseW[o * 128 + c0 + cc];
        }
        if (kg < 8) {
            int s = kg >> 1, q0 = (kg & 1) * 4;
            for (int idx = t; idx < 4096; idx += 256) {
                int cc = idx >> 7, r = idx & 127;
                int ij = r >> 2, kk = r & 3;
                Bs[cc][r] = Wout[((size_t)s * FLAT +
                                  (size_t)(c0 + cc) * 4096 + ij0 + ij) * 8 + q0 + kk];
            }
        } else {
            for (int idx = t; idx < 4096; idx += 256) {
                int cc = idx >> 7, r = idx & 127;
                int ij = r >> 2, kk = r & 3;   // kk == s
                Bs[cc][r] = bout[(size_t)kk * FLAT +
                                 (size_t)(c0 + cc) * 4096 + ij0 + ij];
            }
        }
        __syncthreads();
#pragma unroll 4
        for (int cc = 0; cc < 32; ++cc) {
            float4 av = *(const float4*)&As[cc][4 * to];
            ull aa[4];
            aa[0] = pack2(av.x, av.x);
            aa[1] = pack2(av.y, av.y);
            aa[2] = pack2(av.z, av.z);
            aa[3] = pack2(av.w, av.w);
            const ulonglong2* bp = (const ulonglong2*)&Bs[cc][16 * tn];
            ulonglong2 b01 = bp[0];
            ulonglong2 b23 = bp[1];
            ulonglong2 b45 = bp[2];
            ulonglong2 b67 = bp[3];
            ull bv[8] = {b01.x, b01.y, b23.x, b23.y, b45.x, b45.y, b67.x, b67.y};
#pragma unroll
            for (int oo = 0; oo < 4; ++oo)
#pragma unroll
                for (int m = 0; m < 8; ++m)
                    acc[oo][m] = ffma2(aa[oo], bv[m], acc[oo][m]);
        }
        __syncthreads();
    }

    int kbase = kg * 4;
#pragma unroll
    for (int oo = 0; oo < 4; ++oo) {
        int o = 4 * to + oo;
#pragma unroll
        for (int nl = 0; nl < 4; ++nl) {
            int ij = ij0 + 4 * tn + nl;
            float v0, v1, v2, v3;
            unpack2(acc[oo][nl * 2], v0, v1);
            unpack2(acc[oo][nl * 2 + 1], v2, v3);
            float4 v = make_float4(0.5f * v0, 0.5f * v1, 0.5f * v2, 0.5f * v3);
            *(float4*)&g_G2[((size_t)o * 4096 + ij) * 36 + kbase] = v;
        }
    }
}

// =========================================================================
// kB: finalize q_in, simulate 8-qubit circuit per (s,b), write ev.
// grid (s:4, bh:2), 512 threads = 16 warps; warp -> one (s,b).
// =========================================================================
__device__ __forceinline__ float2 cmul(float2 a, float2 b) {
    return make_float2(a.x * b.x - a.y * b.y, a.x * b.y + a.y * b.x);
}
__device__ __forceinline__ float2 cadd(float2 a, float2 b) {
    return make_float2(a.x + b.x, a.y + b.y);
}

__global__ __launch_bounds__(512) void kB(const float* __restrict__ qinb,
                                          const float* __restrict__ qw) {
    int s = blockIdx.x;
    int bh = blockIdx.y;
    int t = threadIdx.x;
    int w = t >> 5, l = t & 31;
    int b = bh * 16 + w;

    __shared__ float2 st_[16][256];
    float2* sp = st_[w];

    int q = l & 7, pg = l >> 3;
    float sum = 0.f;
    const float* pp = g_partA + (s * 8 + q) * 32 + b;
#pragma unroll 8
    for (int blk = pg; blk < 512; blk += 4) sum += pp[(size_t)blk * 1024];
    sum += __shfl_xor_sync(0xffffffffu, sum, 8);
    sum += __shfl_xor_sync(0xffffffffu, sum, 16);
    float qv = sum + qinb[s * 8 + q];

    for (int tt = 0; tt < 8; ++tt) {
        int p = l + 32 * tt;
        sp[p] = make_float2(p == 0 ? 1.f : 0.f, 0.f);
    }
    __syncwarp();

    for (int qq = 0; qq < 8; ++qq) {
        float ang = 0.5f * __shfl_sync(0xffffffffu, qv, qq);
        float cg = cosf(ang), sg = sinf(ang);
        int pos = 7 - qq, S = 1 << pos;
#pragma unroll
        for (int tt = 0; tt < 4; ++tt) {
            int p = l + 32 * tt;
            int lo = ((p >> pos) << (pos + 1)) | (p & (S - 1));
            int hi = lo | S;
            float2 v0 = sp[lo], v1 = sp[hi];
            sp[lo] = make_float2(cg * v0.x + sg * v1.y, cg * v0.y - sg * v1.x);
            sp[hi] = make_float2(sg * v0.y + cg * v1.x, -sg * v0.x + cg * v1.y);
        }
        __syncwarp();
    }

    for (int lay = 0; lay < 3; ++lay) {
        for (int qq = 0; qq < 8; ++qq) {
            const float* wp = qw + (((size_t)s * 3 + lay) * 8 + qq) * 3;
            float phi = wp[0], th = wp[1], om = wp[2];
            float ct = cosf(0.5f * th), snt = sinf(0.5f * th);
            float ap = -0.5f * (phi + om), am = -0.5f * (phi - om);
            float2 ep = make_float2(cosf(ap), sinf(ap));
            float2 em = make_float2(cosf(am), sinf(am));
            float2 U00 = make_float2(ep.x * ct, ep.y * ct);
            float2 U01 = make_float2(-em.x * snt, em.y * snt);
            float2 U10 = make_float2(em.x * snt, em.y * snt);
            float2 U11 = make_float2(ep.x * ct, -ep.y * ct);
            int pos = 7 - qq, S = 1 << pos;
#pragma unroll
            for (int tt = 0; tt < 4; ++tt) {
                int p = l + 32 * tt;
                int lo = ((p >> pos) << (pos + 1)) | (p & (S - 1));
                int hi = lo | S;
                float2 v0 = sp[lo], v1 = sp[hi];
                sp[lo] = cadd(cmul(U00, v0), cmul(U01, v1));
                sp[hi] = cadd(cmul(U10, v0), cmul(U11, v1));
            }
            __syncwarp();
        }
        for (int e = 0; e < 8; ++e) {
            int ctrl = (e < 7) ? e : 7;
            int tgt = (e < 7) ? e + 1 : 0;
            int pc = 7 - ctrl, pt = 7 - tgt;
            int plo = pc < pt ? pc : pt;
            int phi_ = pc < pt ? pt : pc;
            int Sc = 1 << pc, St = 1 << pt;
#pragma unroll
            for (int tt = 0; tt < 2; ++tt) {
                int r = l + 32 * tt;
                int tmp = ((r >> plo) << (plo + 1)) | (r & ((1 << plo) - 1));
                int p = ((tmp >> phi_) << (phi_ + 1)) | (tmp & ((1 << phi_) - 1));
                p |= Sc;
                float2 a_ = sp[p], b_ = sp[p | St];
                sp[p] = b_; sp[p | St] = a_;
            }
            __syncwarp();
        }
    }

    float evq[8] = {0, 0, 0, 0, 0, 0, 0, 0};
    for (int tt = 0; tt < 8; ++tt) {
        int p = l + 32 * tt;
        float2 v = sp[p];
        float pr = v.x * v.x + v.y * v.y;
#pragma unroll
        for (int qq = 0; qq < 8; ++qq)
            evq[qq] += ((p >> (7 - qq)) & 1) ? -pr : pr;
    }
#pragma unroll
    for (int qq = 0; qq < 8; ++qq)
        for (int off = 16; off; off >>= 1)
            evq[qq] += __shfl_xor_sync(0xffffffffu, evq[qq], off);
    if (l < 8) g_ev[((size_t)s * 32 + b) * 8 + l] = evq[l];
}

// =========================================================================
// kApply: out = x + fuse_b + inverse-Haar butterfly of P (already halved).
// grid (x:128 = ijt*4+bg, y:o:128), 256 threads, 8 batches per block.
// bg fastest-varying so sibling blocks share G2 tile through L2.
// =========================================================================
__global__ __launch_bounds__(256) void kApply(const float* __restrict__ x,
                                              const float* __restrict__ fuseb,
                                              float* __restrict__ out) {
    int bx = blockIdx.x;
    int ijt = bx >> 2;      // 0..31
    int bg = bx & 3;        // 0..3
    int o = blockIdx.y;     // 0..127
    int ij0 = ijt * 128;
    int t = threadIdx.x;

    __shared__ float G2s[128][37];
    __shared__ float evs[8][33];

    const float* gsrc = g_G2 + ((size_t)o * 4096 + ij0) * 36;
    for (int idx = t; idx < 4608; idx += 256) {
        int ij = idx / 36, k = idx - ij * 36;
        G2s[ij][k] = gsrc[idx];
    }
    {
        int bb = t >> 5, k = t & 31;
        if (t < 256)
            evs[bb][k] = g_ev[((size_t)(k >> 3) * 32 + bg * 8 + bb) * 8 + (k & 7)];
    }
    __syncthreads();

    int bi = t >> 7, ijl = t & 127;
    int i_ = ijt * 2 + (ijl >> 6), j_ = ijl & 63;
    float fb = fuseb[o];

    float gr[36];
#pragma unroll
    for (int k = 0; k < 36; ++k) gr[k] = G2s[ijl][k];

#pragma unroll
    for (int bo = 0; bo < 4; ++bo) {
        int bb = bo * 2 + bi;
        int b = bg * 8 + bb;
        const float* er = &evs[bb][0];
        float ps0 = gr[32], ps1 = gr[33], ps2 = gr[34], ps3 = gr[35];
#pragma unroll
        for (int q = 0; q < 8; ++q) {
            ps0 = fmaf(er[q],      gr[q],      ps0);
            ps1 = fmaf(er[8 + q],  gr[8 + q],  ps1);
            ps2 = fmaf(er[16 + q], gr[16 + q], ps2);
            ps3 = fmaf(er[24 + q], gr[24 + q], ps3);
        }
        float t00 = ps0 + ps1 + ps2 + ps3;
        float t01 = ps0 + ps1 - ps2 - ps3;
        float t10 = ps0 - ps1 + ps2 - ps3;
        float t11 = ps0 - ps1 - ps2 + ps3;
        size_t base = (((size_t)b * 128 + o) * 128 + 2 * i_) * 128 + 2 * j_;
        float2 x0 = *(const float2*)(x + base);
        float2 x1 = *(const float2*)(x + base + 128);
        *(float2*)(out + base)       = make_float2(x0.x + fb + t00, x0.y + fb + t01);
        *(float2*)(out + base + 128) = make_float2(x1.x + fb + t10, x1.y + fb + t11);
    }
}

// =========================================================================
extern "C" void kernel_launch(void* const* d_in, const int* in_sizes, int n_in,
                              void* d_out, int out_size) {
    const float* x     = (const float*)d_in[0];
    const float* qinW  = (const float*)d_in[1];
    const float* qinb  = (const float*)d_in[2];
    const float* qw    = (const float*)d_in[3];
    const float* qoutW = (const float*)d_in[4];
    const float* qoutb = (const float*)d_in[5];
    const float* fuseW = (const float*)d_in[6];
    const float* fuseb = (const float*)d_in[7];
    float* out = (float*)d_out;

    kA<<<512, 256>>>(x, qinW);
    kG<<<dim3(128, 9), 256>>>(fuseW, qoutW, qoutb);
    kB<<<dim3(4, 2), 512>>>(qinb, qw);
    kApply<<<dim3(128, 128), 256>>>(x, fuseb, out);
}

// round 4
// speedup vs baseline: 1.2649x; 1.2649x over previous
#include <cuda_runtime.h>
#include <cuda_bf16.h>

#define FLAT 524288          // 128 * 64 * 64

// ---------------- device scratch (no allocation) ----------------
__device__ float g_partA[512 * 1024];                 // [blk][sq(32)][b(32)]
__device__ float g_ev[4 * 32 * 8];                    // [s][b][q]
__device__ float g_G2[(size_t)128 * 4096 * 36];       // [o][ij][k]  ~75.5 MB

// ---------------- packed f32x2 helpers ----------------
typedef unsigned long long ull;
__device__ __forceinline__ ull pack2(float a, float b) {
    ull r; asm("mov.b64 %0, {%1,%2};" : "=l"(r) : "f"(a), "f"(b)); return r;
}
__device__ __forceinline__ void unpack2(ull v, float& a, float& b) {
    asm("mov.b64 {%0,%1}, %2;" : "=f"(a), "=f"(b) : "l"(v));
}
__device__ __forceinline__ ull ffma2(ull a, ull b, ull c) {
    ull d; asm("fma.rn.f32x2 %0, %1, %2, %3;" : "=l"(d) : "l"(a), "l"(b), "l"(c));
    return d;
}

// =========================================================================
// kA: stage-A partial reductions of q_in over (c, 16 subband rows).
// grid 512 = (c:128) x (igroup:4), 256 threads.
// =========================================================================
__global__ __launch_bounds__(256) void kA(const float* __restrict__ x,
                                          const float* __restrict__ Win) {
    int bx = blockIdx.x;
    int c = bx >> 2;
    int i0 = (bx & 3) << 4;
    int t = threadIdx.x, w = t >> 5, l = t & 31;

    __shared__ float subS[4][64][33];   // [s][j][b]
    __shared__ float Ws[64][36];        // [j][sq]

    float acc0 = 0.f, acc1 = 0.f, acc2 = 0.f, acc3 = 0.f;
    int s_w = w >> 1;

    for (int ii = 0; ii < 16; ++ii) {
        int i = i0 + ii;
        const float* wp = Win + (size_t)c * 4096 + (size_t)i * 64;
        for (int idx = t; idx < 2048; idx += 256) {
            int sq = idx >> 6, j = idx & 63;
            Ws[j][sq] = wp[(size_t)sq * FLAT + j];
        }
        for (int pass = 0; pass < 4; ++pass) {
            int b = w + pass * 8;
            const float* xp = x + ((((size_t)b * 128 + c) * 128) + 2 * i) * 128;
            float4 r0 = *(const float4*)(xp + 4 * l);
            float4 r1 = *(const float4*)(xp + 128 + 4 * l);
            int j0 = 2 * l;
            float a = r0.x, bb = r0.y, cc = r1.x, dd = r1.y;
            subS[0][j0][b] = 0.5f * (a + bb + cc + dd);
            subS[1][j0][b] = 0.5f * (a + bb - cc - dd);
            subS[2][j0][b] = 0.5f * (a - bb + cc - dd);
            subS[3][j0][b] = 0.5f * (a - bb - cc + dd);
            a = r0.z; bb = r0.w; cc = r1.z; dd = r1.w;
            subS[0][j0 + 1][b] = 0.5f * (a + bb + cc + dd);
            subS[1][j0 + 1][b] = 0.5f * (a + bb - cc - dd);
            subS[2][j0 + 1][b] = 0.5f * (a - bb + cc - dd);
            subS[3][j0 + 1][b] = 0.5f * (a - bb - cc + dd);
        }
        __syncthreads();
#pragma unroll 8
        for (int j = 0; j < 64; ++j) {
            float4 wv = *(const float4*)&Ws[j][w * 4];
            float sv = subS[s_w][j][l];
            acc0 = fmaf(sv, wv.x, acc0);
            acc1 = fmaf(sv, wv.y, acc1);
            acc2 = fmaf(sv, wv.z, acc2);
            acc3 = fmaf(sv, wv.w, acc3);
        }
        __syncthreads();
    }
    float* op = g_partA + (size_t)bx * 1024 + (w * 4) * 32 + l;
    op[0] = acc0; op[32] = acc1; op[64] = acc2; op[96] = acc3;
}

// =========================================================================
// kG: G2[o][ij][s*8+q] = 0.5 * sum_c fuseW[o,c] * Wout[s][(c,ij)][q]
// grid (ijg:256, s:4, og:2), 256 threads. Block: 64 o x (16 ij x 8 q = 128 n).
// Per thread: 8 o x 4 n, packed f32x2 accumulators.
// =========================================================================
__global__ __launch_bounds__(256) void kG(const float* __restrict__ fuseW,
                                          const float* __restrict__ Wout) {
    __shared__ float As[32][68];    // [cc][o_local]
    __shared__ float Bs[32][128];   // [cc][n]  n = ij*8+q  (coalesced rows)
    int ij0 = blockIdx.x * 16;
    int s = blockIdx.y;
    int o0 = blockIdx.z * 64;
    int t = threadIdx.x;
    int to = t & 31, tn = t >> 5;

    ull acc[8][2];
#pragma unroll
    for (int a = 0; a < 8; ++a) { acc[a][0] = 0ull; acc[a][1] = 0ull; }

    const float* wbase = Wout + (size_t)s * FLAT * 8 + (size_t)ij0 * 8;

    for (int c0 = 0; c0 < 128; c0 += 32) {
        // As[cc][o] : coalesced over cc
        for (int idx = t; idx < 2048; idx += 256) {
            int o = idx >> 5, cc = idx & 31;
            As[cc][o] = fuseW[(o0 + o) * 128 + c0 + cc];
        }
        // Bs[cc][n] : 128 consecutive floats per cc row (fully coalesced)
        for (int idx = t; idx < 4096; idx += 256) {
            int cc = idx >> 7, r = idx & 127;
            Bs[cc][r] = wbase[(size_t)(c0 + cc) * 32768 + r];
        }
        __syncthreads();
#pragma unroll 4
        for (int cc = 0; cc < 32; ++cc) {
            ulonglong2 bv = *(const ulonglong2*)&Bs[cc][4 * to];
            float4 av0 = *(const float4*)&As[cc][tn * 8];
            float4 av1 = *(const float4*)&As[cc][tn * 8 + 4];
            ull aa[8];
            aa[0] = pack2(av0.x, av0.x); aa[1] = pack2(av0.y, av0.y);
            aa[2] = pack2(av0.z, av0.z); aa[3] = pack2(av0.w, av0.w);
            aa[4] = pack2(av1.x, av1.x); aa[5] = pack2(av1.y, av1.y);
            aa[6] = pack2(av1.z, av1.z); aa[7] = pack2(av1.w, av1.w);
#pragma unroll
            for (int oo = 0; oo < 8; ++oo) {
                acc[oo][0] = ffma2(aa[oo], bv.x, acc[oo][0]);
                acc[oo][1] = ffma2(aa[oo], bv.y, acc[oo][1]);
            }
        }
        __syncthreads();
    }

    int ij = ij0 + (to >> 1);
    int q = (to & 1) * 4;
#pragma unroll
    for (int oo = 0; oo < 8; ++oo) {
        int o = o0 + tn * 8 + oo;
        float v0, v1, v2, v3;
        unpack2(acc[oo][0], v0, v1);
        unpack2(acc[oo][1], v2, v3);
        *(float4*)&g_G2[((size_t)o * 4096 + ij) * 36 + s * 8 + q] =
            make_float4(0.5f * v0, 0.5f * v1, 0.5f * v2, 0.5f * v3);
    }
}

// =========================================================================
// kGb: bias slots. G2[o][ij][32+s] = 0.5 * sum_c fuseW[o,c] * bout[s][(c,ij)]
// grid (ijg:128, s:4), 256 threads. Block: 128 o x 32 ij.
// =========================================================================
__global__ __launch_bounds__(256) void kGb(const float* __restrict__ fuseW,
                                           const float* __restrict__ bout) {
    __shared__ float As[32][132];   // [cc][o]
    __shared__ float Bs[32][33];    // [cc][ij]
    int ij0 = blockIdx.x * 32;
    int s = blockIdx.y;
    int t = threadIdx.x;
    int to = t & 31, tn = t >> 5;

    float acc[16];
#pragma unroll
    for (int a = 0; a < 16; ++a) acc[a] = 0.f;

    const float* bbase = bout + (size_t)s * FLAT + ij0;

    for (int c0 = 0; c0 < 128; c0 += 32) {
        for (int idx = t; idx < 4096; idx += 256) {
            int o = idx >> 5, cc = idx & 31;
            As[cc][o] = fuseW[o * 128 + c0 + cc];
        }
        for (int idx = t; idx < 1024; idx += 256) {
            int cc = idx >> 5, ij = idx & 31;
            Bs[cc][ij] = bbase[(size_t)(c0 + cc) * 4096 + ij];
        }
        __syncthreads();
#pragma unroll 4
        for (int cc = 0; cc < 32; ++cc) {
            float bs = Bs[cc][to];
            const float* ap = &As[cc][tn * 16];
#pragma unroll
            for (int oo = 0; oo < 16; ++oo)
                acc[oo] = fmaf(ap[oo], bs, acc[oo]);
        }
        __syncthreads();
    }

    int ij = ij0 + to;
#pragma unroll
    for (int oo = 0; oo < 16; ++oo) {
        int o = tn * 16 + oo;
        g_G2[((size_t)o * 4096 + ij) * 36 + 32 + s] = 0.5f * acc[oo];
    }
}

// =========================================================================
// kB: finalize q_in, simulate 8-qubit circuit per (s,b), write ev.
// grid (s:4, bh:2), 512 threads = 16 warps; warp -> one (s,b).
// =========================================================================
__device__ __forceinline__ float2 cmul(float2 a, float2 b) {
    return make_float2(a.x * b.x - a.y * b.y, a.x * b.y + a.y * b.x);
}
__device__ __forceinline__ float2 cadd(float2 a, float2 b) {
    return make_float2(a.x + b.x, a.y + b.y);
}

__global__ __launch_bounds__(512) void kB(const float* __restrict__ qinb,
                                          const float* __restrict__ qw) {
    int s = blockIdx.x;
    int bh = blockIdx.y;
    int t = threadIdx.x;
    int w = t >> 5, l = t & 31;
    int b = bh * 16 + w;

    __shared__ float2 st_[16][256];
    float2* sp = st_[w];

    int q = l & 7, pg = l >> 3;
    float sum = 0.f;
    const float* pp = g_partA + (s * 8 + q) * 32 + b;
#pragma unroll 8
    for (int blk = pg; blk < 512; blk += 4) sum += pp[(size_t)blk * 1024];
    sum += __shfl_xor_sync(0xffffffffu, sum, 8);
    sum += __shfl_xor_sync(0xffffffffu, sum, 16);
    float qv = sum + qinb[s * 8 + q];

    for (int tt = 0; tt < 8; ++tt) {
        int p = l + 32 * tt;
        sp[p] = make_float2(p == 0 ? 1.f : 0.f, 0.f);
    }
    __syncwarp();

    for (int qq = 0; qq < 8; ++qq) {
        float ang = 0.5f * __shfl_sync(0xffffffffu, qv, qq);
        float cg = cosf(ang), sg = sinf(ang);
        int pos = 7 - qq, S = 1 << pos;
#pragma unroll
        for (int tt = 0; tt < 4; ++tt) {
            int p = l + 32 * tt;
            int lo = ((p >> pos) << (pos + 1)) | (p & (S - 1));
            int hi = lo | S;
            float2 v0 = sp[lo], v1 = sp[hi];
            sp[lo] = make_float2(cg * v0.x + sg * v1.y, cg * v0.y - sg * v1.x);
            sp[hi] = make_float2(sg * v0.y + cg * v1.x, -sg * v0.x + cg * v1.y);
        }
        __syncwarp();
    }

    for (int lay = 0; lay < 3; ++lay) {
        for (int qq = 0; qq < 8; ++qq) {
            const float* wp = qw + (((size_t)s * 3 + lay) * 8 + qq) * 3;
            float phi = wp[0], th = wp[1], om = wp[2];
            float ct = cosf(0.5f * th), snt = sinf(0.5f * th);
            float ap = -0.5f * (phi + om), am = -0.5f * (phi - om);
            float2 ep = make_float2(cosf(ap), sinf(ap));
            float2 em = make_float2(cosf(am), sinf(am));
            float2 U00 = make_float2(ep.x * ct, ep.y * ct);
            float2 U01 = make_float2(-em.x * snt, em.y * snt);
            float2 U10 = make_float2(em.x * snt, em.y * snt);
            float2 U11 = make_float2(ep.x * ct, -ep.y * ct);
            int pos = 7 - qq, S = 1 << pos;
#pragma unroll
            for (int tt = 0; tt < 4; ++tt) {
                int p = l + 32 * tt;
                int lo = ((p >> pos) << (pos + 1)) | (p & (S - 1));
                int hi = lo | S;
                float2 v0 = sp[lo], v1 = sp[hi];
                sp[lo] = cadd(cmul(U00, v0), cmul(U01, v1));
                sp[hi] = cadd(cmul(U10, v0), cmul(U11, v1));
            }
            __syncwarp();
        }
        for (int e = 0; e < 8; ++e) {
            int ctrl = (e < 7) ? e : 7;
            int tgt = (e < 7) ? e + 1 : 0;
            int pc = 7 - ctrl, pt = 7 - tgt;
            int plo = pc < pt ? pc : pt;
            int phi_ = pc < pt ? pt : pc;
            int Sc = 1 << pc, St = 1 << pt;
#pragma unroll
            for (int tt = 0; tt < 2; ++tt) {
                int r = l + 32 * tt;
                int tmp = ((r >> plo) << (plo + 1)) | (r & ((1 << plo) - 1));
                int p = ((tmp >> phi_) << (phi_ + 1)) | (tmp & ((1 << phi_) - 1));
                p |= Sc;
                float2 a_ = sp[p], b_ = sp[p | St];
                sp[p] = b_; sp[p | St] = a_;
            }
            __syncwarp();
        }
    }

    float evq[8] = {0, 0, 0, 0, 0, 0, 0, 0};
    for (int tt = 0; tt < 8; ++tt) {
        int p = l + 32 * tt;
        float2 v = sp[p];
        float pr = v.x * v.x + v.y * v.y;
#pragma unroll
        for (int qq = 0; qq < 8; ++qq)
            evq[qq] += ((p >> (7 - qq)) & 1) ? -pr : pr;
    }
#pragma unroll
    for (int qq = 0; qq < 8; ++qq)
        for (int off = 16; off; off >>= 1)
            evq[qq] += __shfl_xor_sync(0xffffffffu, evq[qq], off);
    if (l < 8) g_ev[((size_t)s * 32 + b) * 8 + l] = evq[l];
}

// =========================================================================
// kApply: out = x + fuse_b + inverse-Haar butterfly of P (already halved).
// grid (ijt:32, o:128), 256 threads, all 32 batches per block, x prefetched.
// =========================================================================
__global__ __launch_bounds__(256) void kApply(const float* __restrict__ x,
                                              const float* __restrict__ fuseb,
                                              float* __restrict__ out) {
    int ijt = blockIdx.x;   // 0..31
    int o = blockIdx.y;     // 0..127
    int ij0 = ijt * 128;
    int t = threadIdx.x;

    __shared__ float G2s[128][37];
    __shared__ float evs[32][33];

    const float* gsrc = g_G2 + ((size_t)o * 4096 + ij0) * 36;
    for (int idx = t; idx < 4608; idx += 256) {
        int ij = idx / 36, k = idx - ij * 36;
        G2s[ij][k] = gsrc[idx];
    }
    for (int idx = t; idx < 1024; idx += 256) {
        int b = idx >> 5, k = idx & 31;
        evs[b][k] = g_ev[((size_t)(k >> 3) * 32 + b) * 8 + (k & 7)];
    }
    __syncthreads();

    int bi = t >> 7, ijl = t & 127;
    int i_ = ijt * 2 + (ijl >> 6), j_ = ijl & 63;
    float fb = fuseb[o];
    const float* gr = &G2s[ijl][0];
    float g32 = gr[32], g33 = gr[33], g34 = gr[34], g35 = gr[35];

    size_t rowoff = ((size_t)o * 128 + 2 * i_) * 128 + 2 * j_;
    // prefetch bo = 0
    size_t base = (size_t)bi * 2097152 + rowoff;
    float2 x0 = *(const float2*)(x + base);
    float2 x1 = *(const float2*)(x + base + 128);

    for (int bo = 0; bo < 16; ++bo) {
        int b = bo * 2 + bi;
        // prefetch next iteration's x
        size_t nbase = base;
        float2 nx0, nx1;
        if (bo < 15) {
            nbase = (size_t)(b + 2) * 2097152 + rowoff;
            nx0 = *(const float2*)(x + nbase);
            nx1 = *(const float2*)(x + nbase + 128);
        }
        const float* er = &evs[b][0];
        float ps0 = g32, ps1 = g33, ps2 = g34, ps3 = g35;
#pragma unroll
        for (int q = 0; q < 8; ++q) {
            ps0 = fmaf(er[q],      gr[q],      ps0);
            ps1 = fmaf(er[8 + q],  gr[8 + q],  ps1);
            ps2 = fmaf(er[16 + q], gr[16 + q], ps2);
            ps3 = fmaf(er[24 + q], gr[24 + q], ps3);
        }
        float t00 = ps0 + ps1 + ps2 + ps3;
        float t01 = ps0 + ps1 - ps2 - ps3;
        float t10 = ps0 - ps1 + ps2 - ps3;
        float t11 = ps0 - ps1 - ps2 + ps3;
        *(float2*)(out + base)       = make_float2(x0.x + fb + t00, x0.y + fb + t01);
        *(float2*)(out + base + 128) = make_float2(x1.x + fb + t10, x1.y + fb + t11);
        base = nbase; x0 = nx0; x1 = nx1;
    }
}

// =========================================================================
extern "C" void kernel_launch(void* const* d_in, const int* in_sizes, int n_in,
                              void* d_out, int out_size) {
    const float* x     = (const float*)d_in[0];
    const float* qinW  = (const float*)d_in[1];
    const float* qinb  = (const float*)d_in[2];
    const float* qw    = (const float*)d_in[3];
    const float* qoutW = (const float*)d_in[4];
    const float* qoutb = (const float*)d_in[5];
    const float* fuseW = (const float*)d_in[6];
    const float* fuseb = (const float*)d_in[7];
    float* out = (float*)d_out;

    kA<<<512, 256>>>(x, qinW);
    kG<<<dim3(256, 4, 2), 256>>>(fuseW, qoutW);
    kGb<<<dim3(128, 4), 256>>>(fuseW, qoutb);
    kB<<<dim3(4, 2), 512>>>(qinb, qw);
    kApply<<<dim3(32, 128), 256>>>(x, fuseb, out);
}

// round 5
// speedup vs baseline: 1.3631x; 1.0776x over previous
#include <cuda_runtime.h>
#include <cuda_bf16.h>

#define FLAT 524288          // 128 * 64 * 64

// ---------------- device scratch (no allocation) ----------------
__device__ float g_partA[512 * 1024];                 // [blk][sq(32)][b(32)]
__device__ float g_ev[4 * 32 * 8];                    // [s][b][q]
__device__ float g_G2[(size_t)128 * 4096 * 36];       // [o][ij][k]  ~75.5 MB

// ---------------- packed f32x2 helpers ----------------
typedef unsigned long long ull;
__device__ __forceinline__ ull pack2(float a, float b) {
    ull r; asm("mov.b64 %0, {%1,%2};" : "=l"(r) : "f"(a), "f"(b)); return r;
}
__device__ __forceinline__ void unpack2(ull v, float& a, float& b) {
    asm("mov.b64 {%0,%1}, %2;" : "=f"(a), "=f"(b) : "l"(v));
}
__device__ __forceinline__ ull ffma2(ull a, ull b, ull c) {
    ull d; asm("fma.rn.f32x2 %0, %1, %2, %3;" : "=l"(d) : "l"(a), "l"(b), "l"(c));
    return d;
}

// =========================================================================
// kA: stage-A partial reductions of q_in over (c, 16 subband rows).
// grid 512 = (c:128) x (igroup:4), 256 threads.
// =========================================================================
__global__ __launch_bounds__(256) void kA(const float* __restrict__ x,
                                          const float* __restrict__ Win) {
    int bx = blockIdx.x;
    int c = bx >> 2;
    int i0 = (bx & 3) << 4;
    int t = threadIdx.x, w = t >> 5, l = t & 31;

    __shared__ float subS[4][64][33];   // [s][j][b]
    __shared__ float Ws[64][36];        // [j][sq]

    float acc0 = 0.f, acc1 = 0.f, acc2 = 0.f, acc3 = 0.f;
    int s_w = w >> 1;

    for (int ii = 0; ii < 16; ++ii) {
        int i = i0 + ii;
        const float* wp = Win + (size_t)c * 4096 + (size_t)i * 64;
        for (int idx = t; idx < 2048; idx += 256) {
            int sq = idx >> 6, j = idx & 63;
            Ws[j][sq] = wp[(size_t)sq * FLAT + j];
        }
        for (int pass = 0; pass < 4; ++pass) {
            int b = w + pass * 8;
            const float* xp = x + ((((size_t)b * 128 + c) * 128) + 2 * i) * 128;
            float4 r0 = *(const float4*)(xp + 4 * l);
            float4 r1 = *(const float4*)(xp + 128 + 4 * l);
            int j0 = 2 * l;
            float a = r0.x, bb = r0.y, cc = r1.x, dd = r1.y;
            subS[0][j0][b] = 0.5f * (a + bb + cc + dd);
            subS[1][j0][b] = 0.5f * (a + bb - cc - dd);
            subS[2][j0][b] = 0.5f * (a - bb + cc - dd);
            subS[3][j0][b] = 0.5f * (a - bb - cc + dd);
            a = r0.z; bb = r0.w; cc = r1.z; dd = r1.w;
            subS[0][j0 + 1][b] = 0.5f * (a + bb + cc + dd);
            subS[1][j0 + 1][b] = 0.5f * (a + bb - cc - dd);
            subS[2][j0 + 1][b] = 0.5f * (a - bb + cc - dd);
            subS[3][j0 + 1][b] = 0.5f * (a - bb - cc + dd);
        }
        __syncthreads();
#pragma unroll 8
        for (int j = 0; j < 64; ++j) {
            float4 wv = *(const float4*)&Ws[j][w * 4];
            float sv = subS[s_w][j][l];
            acc0 = fmaf(sv, wv.x, acc0);
            acc1 = fmaf(sv, wv.y, acc1);
            acc2 = fmaf(sv, wv.z, acc2);
            acc3 = fmaf(sv, wv.w, acc3);
        }
        __syncthreads();
    }
    float* op = g_partA + (size_t)bx * 1024 + (w * 4) * 32 + l;
    op[0] = acc0; op[32] = acc1; op[64] = acc2; op[96] = acc3;
}

// =========================================================================
// kG: G2[o][ij][s*8+q] = 0.5 * sum_c fuseW[o,c] * Wout[s][(c,ij)][q]
// grid (ijg:256, s:4, og:2), 256 threads. Block: 64 o x (16 ij x 8 q = 128 n).
// Per thread: 8 o x 4 n, packed f32x2 accumulators.
// =========================================================================
__global__ __launch_bounds__(256) void kG(const float* __restrict__ fuseW,
                                          const float* __restrict__ Wout) {
    __shared__ float As[32][68];    // [cc][o_local]
    __shared__ float Bs[32][128];   // [cc][n]  n = ij*8+q  (coalesced rows)
    int ij0 = blockIdx.x * 16;
    int s = blockIdx.y;
    int o0 = blockIdx.z * 64;
    int t = threadIdx.x;
    int to = t & 31, tn = t >> 5;

    ull acc[8][2];
#pragma unroll
    for (int a = 0; a < 8; ++a) { acc[a][0] = 0ull; acc[a][1] = 0ull; }

    const float* wbase = Wout + (size_t)s * FLAT * 8 + (size_t)ij0 * 8;

    for (int c0 = 0; c0 < 128; c0 += 32) {
        // As[cc][o] : coalesced over cc
        for (int idx = t; idx < 2048; idx += 256) {
            int o = idx >> 5, cc = idx & 31;
            As[cc][o] = fuseW[(o0 + o) * 128 + c0 + cc];
        }
        // Bs[cc][n] : 128 consecutive floats per cc row (fully coalesced)
        for (int idx = t; idx < 4096; idx += 256) {
            int cc = idx >> 7, r = idx & 127;
            Bs[cc][r] = wbase[(size_t)(c0 + cc) * 32768 + r];
        }
        __syncthreads();
#pragma unroll 4
        for (int cc = 0; cc < 32; ++cc) {
            ulonglong2 bv = *(const ulonglong2*)&Bs[cc][4 * to];
            float4 av0 = *(const float4*)&As[cc][tn * 8];
            float4 av1 = *(const float4*)&As[cc][tn * 8 + 4];
            ull aa[8];
            aa[0] = pack2(av0.x, av0.x); aa[1] = pack2(av0.y, av0.y);
            aa[2] = pack2(av0.z, av0.z); aa[3] = pack2(av0.w, av0.w);
            aa[4] = pack2(av1.x, av1.x); aa[5] = pack2(av1.y, av1.y);
            aa[6] = pack2(av1.z, av1.z); aa[7] = pack2(av1.w, av1.w);
#pragma unroll
            for (int oo = 0; oo < 8; ++oo) {
                acc[oo][0] = ffma2(aa[oo], bv.x, acc[oo][0]);
                acc[oo][1] = ffma2(aa[oo], bv.y, acc[oo][1]);
            }
        }
        __syncthreads();
    }

    int ij = ij0 + (to >> 1);
    int q = (to & 1) * 4;
#pragma unroll
    for (int oo = 0; oo < 8; ++oo) {
        int o = o0 + tn * 8 + oo;
        float v0, v1, v2, v3;
        unpack2(acc[oo][0], v0, v1);
        unpack2(acc[oo][1], v2, v3);
        *(float4*)&g_G2[((size_t)o * 4096 + ij) * 36 + s * 8 + q] =
            make_float4(0.5f * v0, 0.5f * v1, 0.5f * v2, 0.5f * v3);
    }
}

// =========================================================================
// kGb: bias slots. G2[o][ij][32+s] = 0.5 * sum_c fuseW[o,c] * bout[s][(c,ij)]
// grid (ijg:128, s:4), 256 threads. Block: 128 o x 32 ij.
// =========================================================================
__global__ __launch_bounds__(256) void kGb(const float* __restrict__ fuseW,
                                           const float* __restrict__ bout) {
    __shared__ float As[32][132];   // [cc][o]
    __shared__ float Bs[32][33];    // [cc][ij]
    int ij0 = blockIdx.x * 32;
    int s = blockIdx.y;
    int t = threadIdx.x;
    int to = t & 31, tn = t >> 5;

    float acc[16];
#pragma unroll
    for (int a = 0; a < 16; ++a) acc[a] = 0.f;

    const float* bbase = bout + (size_t)s * FLAT + ij0;

    for (int c0 = 0; c0 < 128; c0 += 32) {
        for (int idx = t; idx < 4096; idx += 256) {
            int o = idx >> 5, cc = idx & 31;
            As[cc][o] = fuseW[o * 128 + c0 + cc];
        }
        for (int idx = t; idx < 1024; idx += 256) {
            int cc = idx >> 5, ij = idx & 31;
            Bs[cc][ij] = bbase[(size_t)(c0 + cc) * 4096 + ij];
        }
        __syncthreads();
#pragma unroll 4
        for (int cc = 0; cc < 32; ++cc) {
            float bs = Bs[cc][to];
            const float* ap = &As[cc][tn * 16];
#pragma unroll
            for (int oo = 0; oo < 16; ++oo)
                acc[oo] = fmaf(ap[oo], bs, acc[oo]);
        }
        __syncthreads();
    }

    int ij = ij0 + to;
#pragma unroll
    for (int oo = 0; oo < 16; ++oo) {
        int o = tn * 16 + oo;
        g_G2[((size_t)o * 4096 + ij) * 36 + 32 + s] = 0.5f * acc[oo];
    }
}

// =========================================================================
// kB: finalize q_in, simulate 8-qubit circuit. ONE WARP PER (s,b):
// grid (s:4, b:32), 32 threads. 128 blocks -> one per SM, chains run
// concurrently instead of 4-deep per SMSP.
// =========================================================================
__device__ __forceinline__ float2 cmul(float2 a, float2 b) {
    return make_float2(a.x * b.x - a.y * b.y, a.x * b.y + a.y * b.x);
}
__device__ __forceinline__ float2 cadd(float2 a, float2 b) {
    return make_float2(a.x + b.x, a.y + b.y);
}

__global__ __launch_bounds__(32) void kB(const float* __restrict__ qinb,
                                         const float* __restrict__ qw) {
    int s = blockIdx.x;
    int b = blockIdx.y;
    int l = threadIdx.x;

    __shared__ float2 sp[256];

    // reduce stage-A partials: lane -> (q = l&7, partial group pg = l>>3)
    int q = l & 7, pg = l >> 3;
    float sum = 0.f;
    const float* pp = g_partA + (s * 8 + q) * 32 + b;
#pragma unroll 16
    for (int blk = pg; blk < 512; blk += 4) sum += pp[(size_t)blk * 1024];
    sum += __shfl_xor_sync(0xffffffffu, sum, 8);
    sum += __shfl_xor_sync(0xffffffffu, sum, 16);
    float qv = sum + qinb[s * 8 + q];

    for (int tt = 0; tt < 8; ++tt) {
        int p = l + 32 * tt;
        sp[p] = make_float2(p == 0 ? 1.f : 0.f, 0.f);
    }
    __syncwarp();

    // RX(q_in[q]) on each qubit (qubit q maps to bit 7-q)
    for (int qq = 0; qq < 8; ++qq) {
        float ang = 0.5f * __shfl_sync(0xffffffffu, qv, qq);
        float cg = cosf(ang), sg = sinf(ang);
        int pos = 7 - qq, S = 1 << pos;
#pragma unroll
        for (int tt = 0; tt < 4; ++tt) {
            int p = l + 32 * tt;
            int lo = ((p >> pos) << (pos + 1)) | (p & (S - 1));
            int hi = lo | S;
            float2 v0 = sp[lo], v1 = sp[hi];
            sp[lo] = make_float2(cg * v0.x + sg * v1.y, cg * v0.y - sg * v1.x);
            sp[hi] = make_float2(sg * v0.y + cg * v1.x, -sg * v0.x + cg * v1.y);
        }
        __syncwarp();
    }

    for (int lay = 0; lay < 3; ++lay) {
        for (int qq = 0; qq < 8; ++qq) {
            const float* wp = qw + (((size_t)s * 3 + lay) * 8 + qq) * 3;
            float phi = wp[0], th = wp[1], om = wp[2];
            float ct = cosf(0.5f * th), snt = sinf(0.5f * th);
            float ap = -0.5f * (phi + om), am = -0.5f * (phi - om);
            float2 ep = make_float2(cosf(ap), sinf(ap));
            float2 em = make_float2(cosf(am), sinf(am));
            float2 U00 = make_float2(ep.x * ct, ep.y * ct);
            float2 U01 = make_float2(-em.x * snt, em.y * snt);
            float2 U10 = make_float2(em.x * snt, em.y * snt);
            float2 U11 = make_float2(ep.x * ct, -ep.y * ct);
            int pos = 7 - qq, S = 1 << pos;
#pragma unroll
            for (int tt = 0; tt < 4; ++tt) {
                int p = l + 32 * tt;
                int lo = ((p >> pos) << (pos + 1)) | (p & (S - 1));
                int hi = lo | S;
                float2 v0 = sp[lo], v1 = sp[hi];
                sp[lo] = cadd(cmul(U00, v0), cmul(U01, v1));
                sp[hi] = cadd(cmul(U10, v0), cmul(U11, v1));
            }
            __syncwarp();
        }
        for (int e = 0; e < 8; ++e) {
            int ctrl = (e < 7) ? e : 7;
            int tgt = (e < 7) ? e + 1 : 0;
            int pc = 7 - ctrl, pt = 7 - tgt;
            int plo = pc < pt ? pc : pt;
            int phi_ = pc < pt ? pt : pc;
            int Sc = 1 << pc, St = 1 << pt;
#pragma unroll
            for (int tt = 0; tt < 2; ++tt) {
                int r = l + 32 * tt;
                int tmp = ((r >> plo) << (plo + 1)) | (r & ((1 << plo) - 1));
                int p = ((tmp >> phi_) << (phi_ + 1)) | (tmp & ((1 << phi_) - 1));
                p |= Sc;
                float2 a_ = sp[p], b_ = sp[p | St];
                sp[p] = b_; sp[p | St] = a_;
            }
            __syncwarp();
        }
    }

    float evq[8] = {0, 0, 0, 0, 0, 0, 0, 0};
    for (int tt = 0; tt < 8; ++tt) {
        int p = l + 32 * tt;
        float2 v = sp[p];
        float pr = v.x * v.x + v.y * v.y;
#pragma unroll
        for (int qq = 0; qq < 8; ++qq)
            evq[qq] += ((p >> (7 - qq)) & 1) ? -pr : pr;
    }
#pragma unroll
    for (int qq = 0; qq < 8; ++qq)
        for (int off = 16; off; off >>= 1)
            evq[qq] += __shfl_xor_sync(0xffffffffu, evq[qq], off);
    if (l < 8) g_ev[((size_t)s * 32 + b) * 8 + l] = evq[l];
}

// =========================================================================
// kApply: out = x + fuse_b + inverse-Haar butterfly of P (already halved).
// grid (ijt:32, o:128), 256 threads, all 32 batches per block, x prefetched.
// =========================================================================
__global__ __launch_bounds__(256) void kApply(const float* __restrict__ x,
                                              const float* __restrict__ fuseb,
                                              float* __restrict__ out) {
    int ijt = blockIdx.x;   // 0..31
    int o = blockIdx.y;     // 0..127
    int ij0 = ijt * 128;
    int t = threadIdx.x;

    __shared__ float G2s[128][37];
    __shared__ float evs[32][33];

    const float* gsrc = g_G2 + ((size_t)o * 4096 + ij0) * 36;
    for (int idx = t; idx < 4608; idx += 256) {
        int ij = idx / 36, k = idx - ij * 36;
        G2s[ij][k] = gsrc[idx];
    }
    for (int idx = t; idx < 1024; idx += 256) {
        int b = idx >> 5, k = idx & 31;
        evs[b][k] = g_ev[((size_t)(k >> 3) * 32 + b) * 8 + (k & 7)];
    }
    __syncthreads();

    int bi = t >> 7, ijl = t & 127;
    int i_ = ijt * 2 + (ijl >> 6), j_ = ijl & 63;
    float fb = fuseb[o];
    const float* gr = &G2s[ijl][0];
    float g32 = gr[32], g33 = gr[33], g34 = gr[34], g35 = gr[35];

    size_t rowoff = ((size_t)o * 128 + 2 * i_) * 128 + 2 * j_;
    size_t base = (size_t)bi * 2097152 + rowoff;
    float2 x0 = *(const float2*)(x + base);
    float2 x1 = *(const float2*)(x + base + 128);

    for (int bo = 0; bo < 16; ++bo) {
        int b = bo * 2 + bi;
        size_t nbase = base;
        float2 nx0, nx1;
        if (bo < 15) {
            nbase = (size_t)(b + 2) * 2097152 + rowoff;
            nx0 = *(const float2*)(x + nbase);
            nx1 = *(const float2*)(x + nbase + 128);
        }
        const float* er = &evs[b][0];
        float ps0 = g32, ps1 = g33, ps2 = g34, ps3 = g35;
#pragma unroll
        for (int q = 0; q < 8; ++q) {
            ps0 = fmaf(er[q],      gr[q],      ps0);
            ps1 = fmaf(er[8 + q],  gr[8 + q],  ps1);
            ps2 = fmaf(er[16 + q], gr[16 + q], ps2);
            ps3 = fmaf(er[24 + q], gr[24 + q], ps3);
        }
        float t00 = ps0 + ps1 + ps2 + ps3;
        float t01 = ps0 + ps1 - ps2 - ps3;
        float t10 = ps0 - ps1 + ps2 - ps3;
        float t11 = ps0 - ps1 - ps2 + ps3;
        *(float2*)(out + base)       = make_float2(x0.x + fb + t00, x0.y + fb + t01);
        *(float2*)(out + base + 128) = make_float2(x1.x + fb + t10, x1.y + fb + t11);
        base = nbase; x0 = nx0; x1 = nx1;
    }
}

// =========================================================================
extern "C" void kernel_launch(void* const* d_in, const int* in_sizes, int n_in,
                              void* d_out, int out_size) {
    const float* x     = (const float*)d_in[0];
    const float* qinW  = (const float*)d_in[1];
    const float* qinb  = (const float*)d_in[2];
    const float* qw    = (const float*)d_in[3];
    const float* qoutW = (const float*)d_in[4];
    const float* qoutb = (const float*)d_in[5];
    const float* fuseW = (const float*)d_in[6];
    const float* fuseb = (const float*)d_in[7];
    float* out = (float*)d_out;

    kA<<<512, 256>>>(x, qinW);
    kG<<<dim3(256, 4, 2), 256>>>(fuseW, qoutW);
    kGb<<<dim3(128, 4), 256>>>(fuseW, qoutb);
    kB<<<dim3(4, 32), 32>>>(qinb, qw);
    kApply<<<dim3(32, 128), 256>>>(x, fuseb, out);
}